// round 14
// baseline (speedup 1.0000x reference)
#include <cuda_runtime.h>
#include <cuda_fp16.h>
#include <cstdint>
#include <math.h>
#include <float.h>

// Problem constants
#define BATCH 8
#define SEQ   2048
#define DMODEL 1024
#define EPS_ENT 1e-10f
#define EPS_LN  1e-5f
#define NROWS (BATCH * SEQ)
#define NBLK1 8                       // GEMM1 N-tile blocks per row (SEQ/256)

// ---------------- scratch (allocation-free: __device__ globals) ----------------
__device__ __half g_ph[(size_t)BATCH * SEQ * SEQ];          // 67 MB  unnormalized exp(scores)
__device__ __half g_qh[(size_t)BATCH * SEQ * DMODEL];       // 34 MB
__device__ __half g_kh[(size_t)BATCH * SEQ * DMODEL];       // 34 MB
__device__ __half g_vth[(size_t)BATCH * DMODEL * SEQ];      // 34 MB  V^T fp16
__device__ __half g_wth[(size_t)DMODEL * DMODEL];           // 2 MB   W^T fp16
__device__ __half g_aoh[(size_t)BATCH * SEQ * DMODEL];      // 34 MB  attout fp16
__device__ float  g_psum[(size_t)NROWS * NBLK1];
__device__ float  g_pent[(size_t)NROWS * NBLK1];
__device__ float  g_rowinv[(size_t)NROWS];
__device__ float  g_rowent[(size_t)NROWS];

// ---------------- helpers ----------------
__device__ __forceinline__ void mma_f16(float c[4], const uint32_t a[4], const uint32_t b[2]) {
    asm volatile(
        "mma.sync.aligned.m16n8k16.row.col.f32.f16.f16.f32 "
        "{%0,%1,%2,%3}, {%4,%5,%6,%7}, {%8,%9}, {%0,%1,%2,%3};"
        : "+f"(c[0]), "+f"(c[1]), "+f"(c[2]), "+f"(c[3])
        : "r"(a[0]), "r"(a[1]), "r"(a[2]), "r"(a[3]), "r"(b[0]), "r"(b[1]));
}
__device__ __forceinline__ void ldsm_x4(uint32_t& r0, uint32_t& r1, uint32_t& r2, uint32_t& r3,
                                        uint32_t addr) {
    asm volatile("ldmatrix.sync.aligned.m8n8.x4.shared.b16 {%0,%1,%2,%3}, [%4];"
        : "=r"(r0), "=r"(r1), "=r"(r2), "=r"(r3) : "r"(addr));
}
__device__ __forceinline__ uint32_t smem_u32(const void* p) {
    uint32_t a;
    asm("{ .reg .u64 t; cvta.to.shared.u64 t, %1; cvt.u32.u64 %0, t; }" : "=r"(a) : "l"(p));
    return a;
}
#define CP_ASYNC16(dst, src) \
    asm volatile("cp.async.cg.shared.global [%0], [%1], 16;" :: "r"(dst), "l"(src))
#define CP_COMMIT() asm volatile("cp.async.commit_group;" ::: "memory")
#define CP_WAIT(n)  asm volatile("cp.async.wait_group %0;" :: "n"(n) : "memory")

// =====================================================================
// fp16 mma.sync GEMM:  C = A[M,K] @ B[N,K]^T
// Block tile 128x256, BK=32, 256 threads = 8 warps (2 M x 4 N),
// warp tile 64x64 (min smem traffic per MMA). 4-stage cp.async with
// unconditional-wait steady-state loop, ldmatrix.x4, LDKH=40 pad.
// MODE 0: fp32 out + bias (aux)
// MODE 1: fp16 out = exp(alpha*acc) + deterministic row partials
// MODE 2: fp16 out = acc * rowinv[row] (aux, per batch)
// =====================================================================
#define BM 128
#define BN 256
#define BKK 32
#define LDKH 40
#define A_TILE_B (128 * LDKH * 2)            // 10240 bytes
#define B_TILE_B (256 * LDKH * 2)            // 20480 bytes
#define STAGE_B  (A_TILE_B + B_TILE_B)       // 30720 bytes
#define NSTAGE 4
#define GEMM_SMEM_BYTES (NSTAGE * STAGE_B)   // 122880
#define NTHR 256

template <int MODE>
__global__ __launch_bounds__(NTHR, 1) void gemm_kernel(
    const __half* __restrict__ Ag, const __half* __restrict__ Bg,
    const float* __restrict__ aux, void* __restrict__ Cg,
    float* __restrict__ psum, float* __restrict__ pent,
    int K, long lda, long ldb, long ldc,
    long sA, long sB, long sC, float alpha)
{
    extern __shared__ char smc[];

    const int tid = threadIdx.x;
    const int wid = tid >> 5;
    const int lid = tid & 31;
    const int wm = wid & 1;          // warp M position (0..1)
    const int wn = wid >> 1;         // warp N position (0..3)
    const int g = lid >> 2;
    const int t = lid & 3;

    const long bm = (long)blockIdx.x * BM;
    const long bn = (long)blockIdx.y * BN;
    const __half* A = Ag + (long)blockIdx.z * sA;
    const __half* B = Bg + (long)blockIdx.z * sB;

    const uint32_t sbase = smem_u32(smc);

    const int a_row = lid & 15;
    const int a_koff = (lid >> 4) << 3;
    const int b_row = ((lid >> 4) << 3) + (lid & 7);
    const int b_koff = lid & 8;

    float acc[4][8][4];
#pragma unroll
    for (int mt = 0; mt < 4; ++mt)
#pragma unroll
        for (int nt = 0; nt < 8; ++nt)
#pragma unroll
            for (int c = 0; c < 4; ++c) acc[mt][nt][c] = 0.0f;

    auto copy_stage = [&](int s, long k0) {
        const uint32_t as = sbase + (uint32_t)(s * STAGE_B);
        const uint32_t bs = as + (uint32_t)A_TILE_B;
#pragma unroll
        for (int it = 0; it < 2; ++it) {
            int c = tid + it * NTHR;             // 512 chunks: A 128 rows x 4 (8 halves)
            int m = c >> 2, k8 = (c & 3) << 3;
            CP_ASYNC16(as + (uint32_t)(m * 80 + k8 * 2), &A[(bm + m) * lda + k0 + k8]);
        }
#pragma unroll
        for (int it = 0; it < 4; ++it) {
            int c = tid + it * NTHR;             // 1024 chunks: B 256 rows x 4
            int n = c >> 2, k8 = (c & 3) << 3;
            CP_ASYNC16(bs + (uint32_t)(n * 80 + k8 * 2), &B[(bn + n) * ldb + k0 + k8]);
        }
    };

    auto compute = [&](int s) {
        const uint32_t as = sbase + (uint32_t)(s * STAGE_B);
        const uint32_t bs = as + (uint32_t)A_TILE_B;
#pragma unroll
        for (int ks = 0; ks < 2; ++ks) {
            const int kb = ks * 16;
            uint32_t a[4][4], b[8][2];
#pragma unroll
            for (int mt = 0; mt < 4; ++mt) {
                const int m0 = wm * 64 + mt * 16;
                ldsm_x4(a[mt][0], a[mt][1], a[mt][2], a[mt][3],
                        as + (uint32_t)((m0 + a_row) * 80 + (kb + a_koff) * 2));
            }
#pragma unroll
            for (int np = 0; np < 4; ++np) {
                const int n0 = wn * 64 + np * 16;
                ldsm_x4(b[2 * np][0], b[2 * np][1], b[2 * np + 1][0], b[2 * np + 1][1],
                        bs + (uint32_t)((n0 + b_row) * 80 + (kb + b_koff) * 2));
            }
#pragma unroll
            for (int mt = 0; mt < 4; ++mt)
#pragma unroll
                for (int nt = 0; nt < 8; ++nt)
                    mma_f16(acc[mt][nt], a[mt], b[nt]);
        }
    };

    const int nch = K / BKK;                    // >= 32
    copy_stage(0, 0); CP_COMMIT();
    copy_stage(1, BKK); CP_COMMIT();
    copy_stage(2, 2 * BKK); CP_COMMIT();

    // steady state: unconditional wait(2) + prefetch
    for (int i = 0; i < nch - 3; ++i) {
        CP_WAIT(2);
        __syncthreads();
        copy_stage((i + 3) & (NSTAGE - 1), (long)(i + 3) * BKK); CP_COMMIT();
        compute(i & (NSTAGE - 1));
    }
    // drain: last 3 chunks
    CP_WAIT(2); __syncthreads(); compute((nch - 3) & (NSTAGE - 1));
    CP_WAIT(1); __syncthreads(); compute((nch - 2) & (NSTAGE - 1));
    CP_WAIT(0); __syncthreads(); compute((nch - 1) & (NSTAGE - 1));

    // ================= epilogues =================
    if (MODE == 1) {
        float* sp = (float*)smc;          // [128][4] sum(e)
        float* se = sp + 128 * 4;         // [128][4] sum(e*x)
        __syncthreads();
#pragma unroll
        for (int mt = 0; mt < 4; ++mt) {
            float pe0 = 0.f, pe1 = 0.f, px0 = 0.f, px1 = 0.f;
#pragma unroll
            for (int nt = 0; nt < 8; ++nt) {
                float x0 = acc[mt][nt][0] * alpha, x1 = acc[mt][nt][1] * alpha;
                float x2 = acc[mt][nt][2] * alpha, x3 = acc[mt][nt][3] * alpha;
                float e0 = __expf(x0), e1 = __expf(x1);
                float e2 = __expf(x2), e3 = __expf(x3);
                pe0 += e0 + e1;  px0 += e0 * x0 + e1 * x1;
                pe1 += e2 + e3;  px1 += e2 * x2 + e3 * x3;
                acc[mt][nt][0] = e0; acc[mt][nt][1] = e1;
                acc[mt][nt][2] = e2; acc[mt][nt][3] = e3;
            }
#pragma unroll
            for (int o = 1; o < 4; o <<= 1) {
                pe0 += __shfl_xor_sync(0xffffffffu, pe0, o);
                pe1 += __shfl_xor_sync(0xffffffffu, pe1, o);
                px0 += __shfl_xor_sync(0xffffffffu, px0, o);
                px1 += __shfl_xor_sync(0xffffffffu, px1, o);
            }
            if (t == 0) {
                int r0 = wm * 64 + mt * 16 + g;
                sp[r0 * 4 + wn] = pe0;       se[r0 * 4 + wn] = px0;
                sp[(r0 + 8) * 4 + wn] = pe1; se[(r0 + 8) * 4 + wn] = px1;
            }
        }
        __syncthreads();
        {
            int r = tid & 127, which = tid >> 7;   // 256 threads cover 128 rows x 2 stats
            const float* arr = which ? se : sp;
            float s = 0.f;
#pragma unroll
            for (int j = 0; j < 4; ++j) s += arr[r * 4 + j];
            long gr = (long)blockIdx.z * SEQ + bm + r;
            (which ? pent : psum)[gr * NBLK1 + blockIdx.y] = s;
        }
        __half* Ch = (__half*)Cg + (long)blockIdx.z * sC;
#pragma unroll
        for (int mt = 0; mt < 4; ++mt) {
            const long mrow = bm + wm * 64 + mt * 16;
#pragma unroll
            for (int nt = 0; nt < 8; ++nt) {
                const long col = bn + wn * 64 + nt * 8 + 2 * t;
                *(__half2*)&Ch[(mrow + g) * ldc + col] =
                    __floats2half2_rn(acc[mt][nt][0], acc[mt][nt][1]);
                *(__half2*)&Ch[(mrow + g + 8) * ldc + col] =
                    __floats2half2_rn(acc[mt][nt][2], acc[mt][nt][3]);
            }
        }
    } else if (MODE == 2) {
        const float* rinv = aux + (long)blockIdx.z * SEQ;
        __half* Ch = (__half*)Cg + (long)blockIdx.z * sC;
#pragma unroll
        for (int mt = 0; mt < 4; ++mt) {
            const long mrow = bm + wm * 64 + mt * 16;
            const float i0 = rinv[mrow + g];
            const float i1 = rinv[mrow + g + 8];
#pragma unroll
            for (int nt = 0; nt < 8; ++nt) {
                const long col = bn + wn * 64 + nt * 8 + 2 * t;
                *(__half2*)&Ch[(mrow + g) * ldc + col] =
                    __floats2half2_rn(acc[mt][nt][0] * i0, acc[mt][nt][1] * i0);
                *(__half2*)&Ch[(mrow + g + 8) * ldc + col] =
                    __floats2half2_rn(acc[mt][nt][2] * i1, acc[mt][nt][3] * i1);
            }
        }
    } else {
        float* Cf = (float*)Cg + (long)blockIdx.z * sC;
#pragma unroll
        for (int mt = 0; mt < 4; ++mt) {
            const long mrow = bm + wm * 64 + mt * 16;
#pragma unroll
            for (int nt = 0; nt < 8; ++nt) {
                const long col = bn + wn * 64 + nt * 8 + 2 * t;
                float2 v0, v1;
                v0.x = acc[mt][nt][0] * alpha; v0.y = acc[mt][nt][1] * alpha;
                v1.x = acc[mt][nt][2] * alpha; v1.y = acc[mt][nt][3] * alpha;
                float b0 = aux[col], b1 = aux[col + 1];
                v0.x += b0; v0.y += b1; v1.x += b0; v1.y += b1;
                *(float2*)&Cf[(mrow + g) * ldc + col] = v0;
                *(float2*)&Cf[(mrow + g + 8) * ldc + col] = v1;
            }
        }
    }
}

// =====================================================================
// rowstat: combine partials per row -> rowinv, rowent
// =====================================================================
__global__ __launch_bounds__(256) void rowstat_kernel() {
    int r = blockIdx.x * 256 + threadIdx.x;
    if (r < NROWS) {
        float s = 0.f, w = 0.f;
#pragma unroll
        for (int j = 0; j < NBLK1; ++j) { s += g_psum[r * NBLK1 + j]; w += g_pent[r * NBLK1 + j]; }
        g_rowinv[r] = 1.0f / s;
        g_rowent[r] = __logf(s) - w / s;
    }
}

// =====================================================================
// pre-pass: merged Q/K float -> half (grid.y selects tensor), 4x ILP
// =====================================================================
__global__ __launch_bounds__(512) void f2h2_kernel(
    const float4* __restrict__ in0, const float4* __restrict__ in1,
    __half2* __restrict__ out0, __half2* __restrict__ out1, long n4)
{
    const float4* in = blockIdx.y ? in1 : in0;
    __half2* out = blockIdx.y ? out1 : out0;
    long base = (long)blockIdx.x * 2048 + threadIdx.x;
#pragma unroll
    for (int j = 0; j < 4; ++j) {
        long i = base + j * 512;
        if (i < n4) {
            float4 v = in[i];
            out[2 * i]     = __floats2half2_rn(v.x, v.y);
            out[2 * i + 1] = __floats2half2_rn(v.z, v.w);
        }
    }
}

__global__ __launch_bounds__(256) void transpose_f2h_kernel(
    const float* __restrict__ in, __half* __restrict__ out, int R, int C, long sz)
{
    __shared__ float tbuf[32][33];
    const float* ip = in + (long)blockIdx.z * sz;
    __half* op = out + (long)blockIdx.z * sz;
    int c0 = blockIdx.x * 32, r0 = blockIdx.y * 32;
    int tx = threadIdx.x, ty = threadIdx.y; // 32 x 8
#pragma unroll
    for (int j = 0; j < 32; j += 8) tbuf[ty + j][tx] = ip[(long)(r0 + ty + j) * C + c0 + tx];
    __syncthreads();
#pragma unroll
    for (int j = 0; j < 32; j += 8)
        op[(long)(c0 + ty + j) * R + r0 + tx] = __float2half_rn(tbuf[tx][ty + j]);
}

// =====================================================================
// reductions + syntony + layernorm
// =====================================================================
__device__ __forceinline__ float warpReduceSum(float v) {
#pragma unroll
    for (int o = 16; o > 0; o >>= 1) v += __shfl_xor_sync(0xffffffffu, v, o);
    return v;
}
__device__ __forceinline__ float blockReduceSum(float v) {
    __shared__ float sh[32];
    int lane = threadIdx.x & 31, w = threadIdx.x >> 5;
    v = warpReduceSum(v);
    if (lane == 0) sh[w] = v;
    __syncthreads();
    int nw = (blockDim.x + 31) >> 5;
    float r = (threadIdx.x < nw) ? sh[threadIdx.x] : 0.0f;
    if (w == 0) r = warpReduceSum(r);
    if (threadIdx.x == 0) sh[0] = r;
    __syncthreads();
    float out = sh[0];
    __syncthreads();
    return out;
}

__global__ __launch_bounds__(512) void syntony_kernel(float* __restrict__ out, long tail_off, int tail_cnt) {
    float s = 0.0f;
    for (int i = threadIdx.x; i < NROWS; i += 512) s += g_rowent[i];
    s = blockReduceSum(s);
    if (threadIdx.x == 0) {
        float mean = s / (float)NROWS;
        float syn = 1.0f - mean / logf((float)SEQ);
        syn = fminf(fmaxf(syn, 0.0f), 1.0f);
        for (int i = 0; i < tail_cnt; ++i) out[tail_off + i] = syn;
    }
}

// layernorm, float4 vectorized: 256 threads, one float4 per thread
__global__ __launch_bounds__(256) void layernorm_kernel(
    float* __restrict__ H, const float* __restrict__ gamma, const float* __restrict__ beta)
{
    const long row = blockIdx.x;
    float4* h4 = (float4*)(H + row * (long)DMODEL);
    const int tid = threadIdx.x;
    float4 x = h4[tid];
    float s = x.x + x.y + x.z + x.w;
    s = blockReduceSum(s);
    float mu = s * (1.0f / DMODEL);
    float dx = x.x - mu, dy = x.y - mu, dz = x.z - mu, dw = x.w - mu;
    float v = dx * dx + dy * dy + dz * dz + dw * dw;
    v = blockReduceSum(v);
    float inv = rsqrtf(v * (1.0f / DMODEL) + EPS_LN);
    float4 gm = ((const float4*)gamma)[tid];
    float4 bt = ((const float4*)beta)[tid];
    float4 o;
    o.x = dx * inv * gm.x + bt.x;
    o.y = dy * inv * gm.y + bt.y;
    o.z = dz * inv * gm.z + bt.z;
    o.w = dw * inv * gm.w + bt.w;
    h4[tid] = o;
}

// =====================================================================
// launch
// =====================================================================
extern "C" void kernel_launch(void* const* d_in, const int* in_sizes, int n_in,
                              void* d_out, int out_size) {
    const float* q      = (const float*)d_in[0];
    const float* k      = (const float*)d_in[1];
    const float* v      = (const float*)d_in[2];
    const float* harm_w = (const float*)d_in[3];
    const float* harm_b = (const float*)d_in[4];
    const float* gamma  = (const float*)d_in[5];
    const float* beta   = (const float*)d_in[6];
    float* out = (float*)d_out;

    __half *qh, *kh, *vth, *wth, *ph, *aoh;
    float *psum, *pent, *rowinv;
    cudaGetSymbolAddress((void**)&qh, g_qh);
    cudaGetSymbolAddress((void**)&kh, g_kh);
    cudaGetSymbolAddress((void**)&vth, g_vth);
    cudaGetSymbolAddress((void**)&wth, g_wth);
    cudaGetSymbolAddress((void**)&ph, g_ph);
    cudaGetSymbolAddress((void**)&aoh, g_aoh);
    cudaGetSymbolAddress((void**)&psum, g_psum);
    cudaGetSymbolAddress((void**)&pent, g_pent);
    cudaGetSymbolAddress((void**)&rowinv, g_rowinv);

    cudaFuncSetAttribute(gemm_kernel<0>, cudaFuncAttributeMaxDynamicSharedMemorySize, GEMM_SMEM_BYTES);
    cudaFuncSetAttribute(gemm_kernel<1>, cudaFuncAttributeMaxDynamicSharedMemorySize, GEMM_SMEM_BYTES);
    cudaFuncSetAttribute(gemm_kernel<2>, cudaFuncAttributeMaxDynamicSharedMemorySize, GEMM_SMEM_BYTES);

    static cudaStream_t s1 = nullptr;
    static cudaEvent_t evFork = nullptr, evJoin = nullptr;
    if (!s1) {
        cudaStreamCreateWithFlags(&s1, cudaStreamNonBlocking);
        cudaEventCreateWithFlags(&evFork, cudaEventDisableTiming);
        cudaEventCreateWithFlags(&evJoin, cudaEventDisableTiming);
    }

    const long sQK = (long)SEQ * DMODEL;
    const long sS  = (long)SEQ * SEQ;
    const long BSD = (long)BATCH * SEQ * DMODEL;

    // ---- fork: V/W transpose+convert on side stream (overlaps GEMM1) ----
    cudaEventRecord(evFork, 0);
    cudaStreamWaitEvent(s1, evFork, 0);
    {
        dim3 blk(32, 8);
        transpose_f2h_kernel<<<dim3(DMODEL / 32, DMODEL / 32, 1), blk, 0, s1>>>(
            harm_w, wth, DMODEL, DMODEL, 0L);
        transpose_f2h_kernel<<<dim3(DMODEL / 32, SEQ / 32, BATCH), blk, 0, s1>>>(
            v, vth, SEQ, DMODEL, sQK);
    }
    cudaEventRecord(evJoin, s1);

    // ---- main stream: Q/K convert -> GEMM1 -> rowstat ----
    {
        long n4 = BSD / 4;
        dim3 g2((unsigned)((n4 + 2047) / 2048), 2);
        f2h2_kernel<<<g2, 512>>>((const float4*)q, (const float4*)k,
                                 (__half2*)qh, (__half2*)kh, n4);
    }
    // 1) expP = exp(QK^T/32) fp16 + row partial stats
    {
        dim3 grid(SEQ / BM, SEQ / BN, BATCH);
        gemm_kernel<1><<<grid, NTHR, GEMM_SMEM_BYTES>>>(
            qh, kh, nullptr, ph, psum, pent,
            DMODEL, DMODEL, DMODEL, SEQ, sQK, sQK, sS, 1.0f / 32.0f);
    }
    // 2) row stats
    rowstat_kernel<<<NROWS / 256, 256>>>();
    // 3) syntony scalar -> tail of d_out
    {
        int tail = (int)((long)out_size - BSD);
        if (tail > 0) syntony_kernel<<<1, 512>>>(out, BSD, tail);
    }
    // ---- join: V^T (and W^T) must be ready before GEMM2/GEMM3 ----
    cudaStreamWaitEvent(0, evJoin, 0);
    // 4) attout = (expP @ V) * rowinv  -> fp16
    {
        dim3 grid(SEQ / BM, DMODEL / BN, BATCH);
        gemm_kernel<2><<<grid, NTHR, GEMM_SMEM_BYTES>>>(
            ph, vth, rowinv, aoh, nullptr, nullptr,
            SEQ, SEQ, SEQ, DMODEL, sS, sQK, sQK, 1.0f);
    }
    // 5) h = attout @ W + b -> d_out fp32
    {
        dim3 grid((BATCH * SEQ) / BM, DMODEL / BN, 1);
        gemm_kernel<0><<<grid, NTHR, GEMM_SMEM_BYTES>>>(
            aoh, wth, harm_b, out, nullptr, nullptr,
            DMODEL, DMODEL, DMODEL, DMODEL, 0L, 0L, 0L, 1.0f);
    }
    // 6) layernorm in-place on d_out
    layernorm_kernel<<<BATCH * SEQ, 256>>>(out, gamma, beta);
}

// round 15
// speedup vs baseline: 1.0428x; 1.0428x over previous
#include <cuda_runtime.h>
#include <cuda_fp16.h>
#include <cstdint>
#include <math.h>
#include <float.h>

// Problem constants
#define BATCH 8
#define SEQ   2048
#define DMODEL 1024
#define EPS_ENT 1e-10f
#define EPS_LN  1e-5f
#define NROWS (BATCH * SEQ)
#define NBLK1 8                       // GEMM1 N-blocks per row (SEQ/256)
#define NBLK3 4                       // GEMM3 N-blocks per row (DMODEL/256)

// ---------------- scratch (allocation-free: __device__ globals) ----------------
__device__ __half g_ph[(size_t)BATCH * SEQ * SEQ];          // 67 MB  unnormalized exp(scores)
__device__ __half g_qh[(size_t)BATCH * SEQ * DMODEL];       // 34 MB
__device__ __half g_kh[(size_t)BATCH * SEQ * DMODEL];       // 34 MB
__device__ __half g_vth[(size_t)BATCH * DMODEL * SEQ];      // 34 MB  V^T fp16
__device__ __half g_wth[(size_t)DMODEL * DMODEL];           // 2 MB   W^T fp16
__device__ __half g_aoh[(size_t)BATCH * SEQ * DMODEL];      // 34 MB  attout fp16
__device__ float  g_psum[(size_t)NROWS * NBLK1];
__device__ float  g_pent[(size_t)NROWS * NBLK1];
__device__ float  g_rowinv[(size_t)NROWS];
__device__ float  g_rowent[(size_t)NROWS];
__device__ float  g_hsum[(size_t)NROWS * NBLK3];            // LN partial sum(h)
__device__ float  g_hsq[(size_t)NROWS * NBLK3];             // LN partial sum(h^2)

// ---------------- helpers ----------------
__device__ __forceinline__ void mma_f16(float c[4], const uint32_t a[4], const uint32_t b[2]) {
    asm volatile(
        "mma.sync.aligned.m16n8k16.row.col.f32.f16.f16.f32 "
        "{%0,%1,%2,%3}, {%4,%5,%6,%7}, {%8,%9}, {%0,%1,%2,%3};"
        : "+f"(c[0]), "+f"(c[1]), "+f"(c[2]), "+f"(c[3])
        : "r"(a[0]), "r"(a[1]), "r"(a[2]), "r"(a[3]), "r"(b[0]), "r"(b[1]));
}
__device__ __forceinline__ void ldsm_x4(uint32_t& r0, uint32_t& r1, uint32_t& r2, uint32_t& r3,
                                        uint32_t addr) {
    asm volatile("ldmatrix.sync.aligned.m8n8.x4.shared.b16 {%0,%1,%2,%3}, [%4];"
        : "=r"(r0), "=r"(r1), "=r"(r2), "=r"(r3) : "r"(addr));
}
__device__ __forceinline__ uint32_t smem_u32(const void* p) {
    uint32_t a;
    asm("{ .reg .u64 t; cvta.to.shared.u64 t, %1; cvt.u32.u64 %0, t; }" : "=r"(a) : "l"(p));
    return a;
}
#define CP_ASYNC16(dst, src) \
    asm volatile("cp.async.cg.shared.global [%0], [%1], 16;" :: "r"(dst), "l"(src))
#define CP_COMMIT() asm volatile("cp.async.commit_group;" ::: "memory")
#define CP_WAIT(n)  asm volatile("cp.async.wait_group %0;" :: "n"(n) : "memory")

// =====================================================================
// fp16 mma.sync GEMM:  C = A[M,K] @ B[N,K]^T
// Block tile 128x256, BK=32, 512 threads = 16 warps (2 M x 8 N),
// warp tile 64x32. 4-stage cp.async, unconditional-wait steady loop,
// ldmatrix.x4, LDKH=40 pad (conflict-free).
// MODE 0: fp32 out + bias (aux); deterministic LN partials -> g_hsum/g_hsq
// MODE 1: fp16 out = exp(alpha*acc) + deterministic row partials
// MODE 2: fp16 out = acc * rowinv[row] (aux, per batch)
// =====================================================================
#define BM 128
#define BN 256
#define BKK 32
#define LDKH 40
#define A_TILE_B (128 * LDKH * 2)            // 10240 bytes
#define B_TILE_B (256 * LDKH * 2)            // 20480 bytes
#define STAGE_B  (A_TILE_B + B_TILE_B)       // 30720 bytes
#define NSTAGE 4
#define GEMM_SMEM_BYTES (NSTAGE * STAGE_B)   // 122880
#define NTHR 512

template <int MODE>
__global__ __launch_bounds__(NTHR, 1) void gemm_kernel(
    const __half* __restrict__ Ag, const __half* __restrict__ Bg,
    const float* __restrict__ aux, void* __restrict__ Cg,
    float* __restrict__ psum, float* __restrict__ pent,
    int K, long lda, long ldb, long ldc,
    long sA, long sB, long sC, float alpha)
{
    extern __shared__ char smc[];

    const int tid = threadIdx.x;
    const int wid = tid >> 5;
    const int lid = tid & 31;
    const int wm = wid & 1;
    const int wn = wid >> 1;
    const int g = lid >> 2;
    const int t = lid & 3;

    const long bm = (long)blockIdx.x * BM;
    const long bn = (long)blockIdx.y * BN;
    const __half* A = Ag + (long)blockIdx.z * sA;
    const __half* B = Bg + (long)blockIdx.z * sB;

    const uint32_t sbase = smem_u32(smc);

    const int a_row = lid & 15;
    const int a_koff = (lid >> 4) << 3;
    const int b_row = ((lid >> 4) << 3) + (lid & 7);
    const int b_koff = lid & 8;

    float acc[4][4][4];
#pragma unroll
    for (int mt = 0; mt < 4; ++mt)
#pragma unroll
        for (int nt = 0; nt < 4; ++nt)
#pragma unroll
            for (int c = 0; c < 4; ++c) acc[mt][nt][c] = 0.0f;

    auto copy_stage = [&](int s, long k0) {
        const uint32_t as = sbase + (uint32_t)(s * STAGE_B);
        const uint32_t bs = as + (uint32_t)A_TILE_B;
        {
            int c = tid;
            int m = c >> 2, k8 = (c & 3) << 3;
            CP_ASYNC16(as + (uint32_t)(m * 80 + k8 * 2), &A[(bm + m) * lda + k0 + k8]);
        }
#pragma unroll
        for (int it = 0; it < 2; ++it) {
            int c = tid + it * NTHR;
            int n = c >> 2, k8 = (c & 3) << 3;
            CP_ASYNC16(bs + (uint32_t)(n * 80 + k8 * 2), &B[(bn + n) * ldb + k0 + k8]);
        }
    };

    auto compute = [&](int s) {
        const uint32_t as = sbase + (uint32_t)(s * STAGE_B);
        const uint32_t bs = as + (uint32_t)A_TILE_B;
#pragma unroll
        for (int ks = 0; ks < 2; ++ks) {
            const int kb = ks * 16;
            uint32_t a[4][4], b[4][2];
#pragma unroll
            for (int mt = 0; mt < 4; ++mt) {
                const int m0 = wm * 64 + mt * 16;
                ldsm_x4(a[mt][0], a[mt][1], a[mt][2], a[mt][3],
                        as + (uint32_t)((m0 + a_row) * 80 + (kb + a_koff) * 2));
            }
#pragma unroll
            for (int np = 0; np < 2; ++np) {
                const int n0 = wn * 32 + np * 16;
                ldsm_x4(b[2 * np][0], b[2 * np][1], b[2 * np + 1][0], b[2 * np + 1][1],
                        bs + (uint32_t)((n0 + b_row) * 80 + (kb + b_koff) * 2));
            }
#pragma unroll
            for (int mt = 0; mt < 4; ++mt)
#pragma unroll
                for (int nt = 0; nt < 4; ++nt)
                    mma_f16(acc[mt][nt], a[mt], b[nt]);
        }
    };

    const int nch = K / BKK;                    // >= 32
    copy_stage(0, 0); CP_COMMIT();
    copy_stage(1, BKK); CP_COMMIT();
    copy_stage(2, 2 * BKK); CP_COMMIT();

    for (int i = 0; i < nch - 3; ++i) {
        CP_WAIT(2);
        __syncthreads();
        copy_stage((i + 3) & (NSTAGE - 1), (long)(i + 3) * BKK); CP_COMMIT();
        compute(i & (NSTAGE - 1));
    }
    CP_WAIT(2); __syncthreads(); compute((nch - 3) & (NSTAGE - 1));
    CP_WAIT(1); __syncthreads(); compute((nch - 2) & (NSTAGE - 1));
    CP_WAIT(0); __syncthreads(); compute((nch - 1) & (NSTAGE - 1));

    // ================= epilogues =================
    if (MODE == 1) {
        float* sp = (float*)smc;          // [128][8] sum(e)
        float* se = sp + 128 * 8;         // [128][8] sum(e*x)
        __syncthreads();
#pragma unroll
        for (int mt = 0; mt < 4; ++mt) {
            float pe0 = 0.f, pe1 = 0.f, px0 = 0.f, px1 = 0.f;
#pragma unroll
            for (int nt = 0; nt < 4; ++nt) {
                float x0 = acc[mt][nt][0] * alpha, x1 = acc[mt][nt][1] * alpha;
                float x2 = acc[mt][nt][2] * alpha, x3 = acc[mt][nt][3] * alpha;
                float e0 = __expf(x0), e1 = __expf(x1);
                float e2 = __expf(x2), e3 = __expf(x3);
                pe0 += e0 + e1;  px0 += e0 * x0 + e1 * x1;
                pe1 += e2 + e3;  px1 += e2 * x2 + e3 * x3;
                acc[mt][nt][0] = e0; acc[mt][nt][1] = e1;
                acc[mt][nt][2] = e2; acc[mt][nt][3] = e3;
            }
#pragma unroll
            for (int o = 1; o < 4; o <<= 1) {
                pe0 += __shfl_xor_sync(0xffffffffu, pe0, o);
                pe1 += __shfl_xor_sync(0xffffffffu, pe1, o);
                px0 += __shfl_xor_sync(0xffffffffu, px0, o);
                px1 += __shfl_xor_sync(0xffffffffu, px1, o);
            }
            if (t == 0) {
                int r0 = wm * 64 + mt * 16 + g;
                sp[r0 * 8 + wn] = pe0;       se[r0 * 8 + wn] = px0;
                sp[(r0 + 8) * 8 + wn] = pe1; se[(r0 + 8) * 8 + wn] = px1;
            }
        }
        __syncthreads();
        if (tid < 256) {
            int r = tid & 127, which = tid >> 7;
            const float* arr = which ? se : sp;
            float s = 0.f;
#pragma unroll
            for (int j = 0; j < 8; ++j) s += arr[r * 8 + j];
            long gr = (long)blockIdx.z * SEQ + bm + r;
            (which ? pent : psum)[gr * NBLK1 + blockIdx.y] = s;
        }
        __half* Ch = (__half*)Cg + (long)blockIdx.z * sC;
#pragma unroll
        for (int mt = 0; mt < 4; ++mt) {
            const long mrow = bm + wm * 64 + mt * 16;
#pragma unroll
            for (int nt = 0; nt < 4; ++nt) {
                const long col = bn + wn * 32 + nt * 8 + 2 * t;
                *(__half2*)&Ch[(mrow + g) * ldc + col] =
                    __floats2half2_rn(acc[mt][nt][0], acc[mt][nt][1]);
                *(__half2*)&Ch[(mrow + g + 8) * ldc + col] =
                    __floats2half2_rn(acc[mt][nt][2], acc[mt][nt][3]);
            }
        }
    } else if (MODE == 2) {
        const float* rinv = aux + (long)blockIdx.z * SEQ;
        __half* Ch = (__half*)Cg + (long)blockIdx.z * sC;
#pragma unroll
        for (int mt = 0; mt < 4; ++mt) {
            const long mrow = bm + wm * 64 + mt * 16;
            const float i0 = rinv[mrow + g];
            const float i1 = rinv[mrow + g + 8];
#pragma unroll
            for (int nt = 0; nt < 4; ++nt) {
                const long col = bn + wn * 32 + nt * 8 + 2 * t;
                *(__half2*)&Ch[(mrow + g) * ldc + col] =
                    __floats2half2_rn(acc[mt][nt][0] * i0, acc[mt][nt][1] * i0);
                *(__half2*)&Ch[(mrow + g + 8) * ldc + col] =
                    __floats2half2_rn(acc[mt][nt][2] * i1, acc[mt][nt][3] * i1);
            }
        }
    } else {
        // MODE 0: write h (fp32, +bias) and deterministic LN partials
        float* hs = (float*)smc;          // [128][8] sum(h)
        float* hq = hs + 128 * 8;         // [128][8] sum(h^2)
        __syncthreads();
        float* Cf = (float*)Cg + (long)blockIdx.z * sC;
#pragma unroll
        for (int mt = 0; mt < 4; ++mt) {
            const long mrow = bm + wm * 64 + mt * 16;
            float s0 = 0.f, q0 = 0.f, s1 = 0.f, q1 = 0.f;
#pragma unroll
            for (int nt = 0; nt < 4; ++nt) {
                const long col = bn + wn * 32 + nt * 8 + 2 * t;
                float b0 = aux[col], b1 = aux[col + 1];
                float2 v0, v1;
                v0.x = acc[mt][nt][0] * alpha + b0; v0.y = acc[mt][nt][1] * alpha + b1;
                v1.x = acc[mt][nt][2] * alpha + b0; v1.y = acc[mt][nt][3] * alpha + b1;
                s0 += v0.x + v0.y;  q0 += v0.x * v0.x + v0.y * v0.y;
                s1 += v1.x + v1.y;  q1 += v1.x * v1.x + v1.y * v1.y;
                *(float2*)&Cf[(mrow + g) * ldc + col] = v0;
                *(float2*)&Cf[(mrow + g + 8) * ldc + col] = v1;
            }
#pragma unroll
            for (int o = 1; o < 4; o <<= 1) {
                s0 += __shfl_xor_sync(0xffffffffu, s0, o);
                q0 += __shfl_xor_sync(0xffffffffu, q0, o);
                s1 += __shfl_xor_sync(0xffffffffu, s1, o);
                q1 += __shfl_xor_sync(0xffffffffu, q1, o);
            }
            if (t == 0) {
                int r0 = wm * 64 + mt * 16 + g;
                hs[r0 * 8 + wn] = s0;       hq[r0 * 8 + wn] = q0;
                hs[(r0 + 8) * 8 + wn] = s1; hq[(r0 + 8) * 8 + wn] = q1;
            }
        }
        __syncthreads();
        if (tid < 256) {
            int r = tid & 127, which = tid >> 7;
            const float* arr = which ? hq : hs;
            float s = 0.f;
#pragma unroll
            for (int j = 0; j < 8; ++j) s += arr[r * 8 + j];
            long gr = bm + r;   // MODE 0 runs with blockIdx.z == 0, M = NROWS
            (which ? g_hsq : g_hsum)[gr * NBLK3 + blockIdx.y] = s;
        }
    }
}

// =====================================================================
// rowstat: combine partials per row -> rowinv, rowent
// =====================================================================
__global__ __launch_bounds__(256) void rowstat_kernel() {
    int r = blockIdx.x * 256 + threadIdx.x;
    if (r < NROWS) {
        float s = 0.f, w = 0.f;
#pragma unroll
        for (int j = 0; j < NBLK1; ++j) { s += g_psum[r * NBLK1 + j]; w += g_pent[r * NBLK1 + j]; }
        g_rowinv[r] = 1.0f / s;
        g_rowent[r] = __logf(s) - w / s;
    }
}

// =====================================================================
// pre-pass: merged Q/K float -> half (grid.y selects tensor), 4x ILP
// =====================================================================
__global__ __launch_bounds__(512) void f2h2_kernel(
    const float4* __restrict__ in0, const float4* __restrict__ in1,
    __half2* __restrict__ out0, __half2* __restrict__ out1, long n4)
{
    const float4* in = blockIdx.y ? in1 : in0;
    __half2* out = blockIdx.y ? out1 : out0;
    long base = (long)blockIdx.x * 2048 + threadIdx.x;
#pragma unroll
    for (int j = 0; j < 4; ++j) {
        long i = base + j * 512;
        if (i < n4) {
            float4 v = in[i];
            out[2 * i]     = __floats2half2_rn(v.x, v.y);
            out[2 * i + 1] = __floats2half2_rn(v.z, v.w);
        }
    }
}

__global__ __launch_bounds__(256) void transpose_f2h_kernel(
    const float* __restrict__ in, __half* __restrict__ out, int R, int C, long sz)
{
    __shared__ float tbuf[32][33];
    const float* ip = in + (long)blockIdx.z * sz;
    __half* op = out + (long)blockIdx.z * sz;
    int c0 = blockIdx.x * 32, r0 = blockIdx.y * 32;
    int tx = threadIdx.x, ty = threadIdx.y; // 32 x 8
#pragma unroll
    for (int j = 0; j < 32; j += 8) tbuf[ty + j][tx] = ip[(long)(r0 + ty + j) * C + c0 + tx];
    __syncthreads();
#pragma unroll
    for (int j = 0; j < 32; j += 8)
        op[(long)(c0 + ty + j) * R + r0 + tx] = __float2half_rn(tbuf[tx][ty + j]);
}

// =====================================================================
// reductions + syntony + layernorm
// =====================================================================
__device__ __forceinline__ float warpReduceSum(float v) {
#pragma unroll
    for (int o = 16; o > 0; o >>= 1) v += __shfl_xor_sync(0xffffffffu, v, o);
    return v;
}
__device__ __forceinline__ float blockReduceSum(float v) {
    __shared__ float sh[32];
    int lane = threadIdx.x & 31, w = threadIdx.x >> 5;
    v = warpReduceSum(v);
    if (lane == 0) sh[w] = v;
    __syncthreads();
    int nw = (blockDim.x + 31) >> 5;
    float r = (threadIdx.x < nw) ? sh[threadIdx.x] : 0.0f;
    if (w == 0) r = warpReduceSum(r);
    if (threadIdx.x == 0) sh[0] = r;
    __syncthreads();
    float out = sh[0];
    __syncthreads();
    return out;
}

__global__ __launch_bounds__(512) void syntony_kernel(float* __restrict__ out, long tail_off, int tail_cnt) {
    float s = 0.0f;
    for (int i = threadIdx.x; i < NROWS; i += 512) s += g_rowent[i];
    s = blockReduceSum(s);
    if (threadIdx.x == 0) {
        float mean = s / (float)NROWS;
        float syn = 1.0f - mean / logf((float)SEQ);
        syn = fminf(fmaxf(syn, 0.0f), 1.0f);
        for (int i = 0; i < tail_cnt; ++i) out[tail_off + i] = syn;
    }
}

// layernorm using precomputed partials: pure streaming pass, no reductions
__global__ __launch_bounds__(256) void layernorm_kernel(
    float* __restrict__ H, const float* __restrict__ gamma, const float* __restrict__ beta)
{
    const long row = blockIdx.x;
    float s = 0.f, q = 0.f;
#pragma unroll
    for (int j = 0; j < NBLK3; ++j) { s += g_hsum[row * NBLK3 + j]; q += g_hsq[row * NBLK3 + j]; }
    const float mu = s * (1.0f / DMODEL);
    const float var = fmaxf(q * (1.0f / DMODEL) - mu * mu, 0.0f);
    const float inv = rsqrtf(var + EPS_LN);

    float4* h4 = (float4*)(H + row * (long)DMODEL);
    const int tid = threadIdx.x;
    float4 x = h4[tid];
    float4 gm = ((const float4*)gamma)[tid];
    float4 bt = ((const float4*)beta)[tid];
    float4 o;
    o.x = (x.x - mu) * inv * gm.x + bt.x;
    o.y = (x.y - mu) * inv * gm.y + bt.y;
    o.z = (x.z - mu) * inv * gm.z + bt.z;
    o.w = (x.w - mu) * inv * gm.w + bt.w;
    h4[tid] = o;
}

// =====================================================================
// launch
// =====================================================================
extern "C" void kernel_launch(void* const* d_in, const int* in_sizes, int n_in,
                              void* d_out, int out_size) {
    const float* q      = (const float*)d_in[0];
    const float* k      = (const float*)d_in[1];
    const float* v      = (const float*)d_in[2];
    const float* harm_w = (const float*)d_in[3];
    const float* harm_b = (const float*)d_in[4];
    const float* gamma  = (const float*)d_in[5];
    const float* beta   = (const float*)d_in[6];
    float* out = (float*)d_out;

    __half *qh, *kh, *vth, *wth, *ph, *aoh;
    float *psum, *pent, *rowinv;
    cudaGetSymbolAddress((void**)&qh, g_qh);
    cudaGetSymbolAddress((void**)&kh, g_kh);
    cudaGetSymbolAddress((void**)&vth, g_vth);
    cudaGetSymbolAddress((void**)&wth, g_wth);
    cudaGetSymbolAddress((void**)&ph, g_ph);
    cudaGetSymbolAddress((void**)&aoh, g_aoh);
    cudaGetSymbolAddress((void**)&psum, g_psum);
    cudaGetSymbolAddress((void**)&pent, g_pent);
    cudaGetSymbolAddress((void**)&rowinv, g_rowinv);

    cudaFuncSetAttribute(gemm_kernel<0>, cudaFuncAttributeMaxDynamicSharedMemorySize, GEMM_SMEM_BYTES);
    cudaFuncSetAttribute(gemm_kernel<1>, cudaFuncAttributeMaxDynamicSharedMemorySize, GEMM_SMEM_BYTES);
    cudaFuncSetAttribute(gemm_kernel<2>, cudaFuncAttributeMaxDynamicSharedMemorySize, GEMM_SMEM_BYTES);

    static cudaStream_t s1 = nullptr;
    static cudaEvent_t evFork = nullptr, evJoin = nullptr;
    if (!s1) {
        cudaStreamCreateWithFlags(&s1, cudaStreamNonBlocking);
        cudaEventCreateWithFlags(&evFork, cudaEventDisableTiming);
        cudaEventCreateWithFlags(&evJoin, cudaEventDisableTiming);
    }

    const long sQK = (long)SEQ * DMODEL;
    const long sS  = (long)SEQ * SEQ;
    const long BSD = (long)BATCH * SEQ * DMODEL;

    // ---- fork: V/W transpose+convert on side stream (overlaps GEMM1) ----
    cudaEventRecord(evFork, 0);
    cudaStreamWaitEvent(s1, evFork, 0);
    {
        dim3 blk(32, 8);
        transpose_f2h_kernel<<<dim3(DMODEL / 32, DMODEL / 32, 1), blk, 0, s1>>>(
            harm_w, wth, DMODEL, DMODEL, 0L);
        transpose_f2h_kernel<<<dim3(DMODEL / 32, SEQ / 32, BATCH), blk, 0, s1>>>(
            v, vth, SEQ, DMODEL, sQK);
    }
    cudaEventRecord(evJoin, s1);

    // ---- main stream: Q/K convert -> GEMM1 -> rowstat ----
    {
        long n4 = BSD / 4;
        dim3 g2((unsigned)((n4 + 2047) / 2048), 2);
        f2h2_kernel<<<g2, 512>>>((const float4*)q, (const float4*)k,
                                 (__half2*)qh, (__half2*)kh, n4);
    }
    // 1) expP = exp(QK^T/32) fp16 + row partial stats
    {
        dim3 grid(SEQ / BM, SEQ / BN, BATCH);
        gemm_kernel<1><<<grid, NTHR, GEMM_SMEM_BYTES>>>(
            qh, kh, nullptr, ph, psum, pent,
            DMODEL, DMODEL, DMODEL, SEQ, sQK, sQK, sS, 1.0f / 32.0f);
    }
    // 2) row stats
    rowstat_kernel<<<NROWS / 256, 256>>>();
    // 3) syntony scalar -> tail of d_out
    {
        int tail = (int)((long)out_size - BSD);
        if (tail > 0) syntony_kernel<<<1, 512>>>(out, BSD, tail);
    }
    // ---- join: V^T / W^T ready before GEMM2/GEMM3 ----
    cudaStreamWaitEvent(0, evJoin, 0);
    // 4) attout = (expP @ V) * rowinv  -> fp16
    {
        dim3 grid(SEQ / BM, DMODEL / BN, BATCH);
        gemm_kernel<2><<<grid, NTHR, GEMM_SMEM_BYTES>>>(
            ph, vth, rowinv, aoh, nullptr, nullptr,
            SEQ, SEQ, SEQ, DMODEL, sS, sQK, sQK, 1.0f);
    }
    // 5) h = attout @ W + b -> d_out fp32, + LN partial stats
    {
        dim3 grid((BATCH * SEQ) / BM, DMODEL / BN, 1);
        gemm_kernel<0><<<grid, NTHR, GEMM_SMEM_BYTES>>>(
            aoh, wth, harm_b, out, nullptr, nullptr,
            DMODEL, DMODEL, DMODEL, DMODEL, 0L, 0L, 0L, 1.0f);
    }
    // 6) layernorm in-place on d_out (streaming; stats precomputed)
    layernorm_kernel<<<BATCH * SEQ, 256>>>(out, gamma, beta);
}

// round 16
// speedup vs baseline: 1.1452x; 1.0982x over previous
#include <cuda_runtime.h>
#include <cuda_fp16.h>
#include <cstdint>
#include <math.h>
#include <float.h>

// Problem constants
#define BATCH 8
#define SEQ   2048
#define DMODEL 1024
#define EPS_ENT 1e-10f
#define EPS_LN  1e-5f
#define NROWS (BATCH * SEQ)
#define NBLK1 8                       // GEMM1 N-blocks per row (SEQ/256)
#define NBLK3 4                       // GEMM3 N-blocks per row (DMODEL/256)

// ---------------- scratch (allocation-free: __device__ globals) ----------------
__device__ __half g_ph[(size_t)BATCH * SEQ * SEQ];          // 67 MB  unnormalized exp(scores)
__device__ __half g_qh[(size_t)BATCH * SEQ * DMODEL];       // 34 MB
__device__ __half g_kh[(size_t)BATCH * SEQ * DMODEL];       // 34 MB
__device__ __half g_vth[(size_t)BATCH * DMODEL * SEQ];      // 34 MB  V^T fp16
__device__ __half g_wth[(size_t)DMODEL * DMODEL];           // 2 MB   W^T fp16
__device__ __half g_aoh[(size_t)BATCH * SEQ * DMODEL];      // 34 MB  attout fp16
__device__ float  g_psum[(size_t)NROWS * NBLK1];
__device__ float  g_pent[(size_t)NROWS * NBLK1];
__device__ float  g_rowinv[(size_t)NROWS];
__device__ float  g_rowent[(size_t)NROWS];
__device__ float  g_hsum[(size_t)NROWS * NBLK3];            // LN partial sum(h)
__device__ float  g_hsq[(size_t)NROWS * NBLK3];             // LN partial sum(h^2)

// ---------------- helpers ----------------
__device__ __forceinline__ void mma_f16(float c[4], const uint32_t a[4], const uint32_t b[2]) {
    asm volatile(
        "mma.sync.aligned.m16n8k16.row.col.f32.f16.f16.f32 "
        "{%0,%1,%2,%3}, {%4,%5,%6,%7}, {%8,%9}, {%0,%1,%2,%3};"
        : "+f"(c[0]), "+f"(c[1]), "+f"(c[2]), "+f"(c[3])
        : "r"(a[0]), "r"(a[1]), "r"(a[2]), "r"(a[3]), "r"(b[0]), "r"(b[1]));
}
__device__ __forceinline__ void ldsm_x4(uint32_t& r0, uint32_t& r1, uint32_t& r2, uint32_t& r3,
                                        uint32_t addr) {
    asm volatile("ldmatrix.sync.aligned.m8n8.x4.shared.b16 {%0,%1,%2,%3}, [%4];"
        : "=r"(r0), "=r"(r1), "=r"(r2), "=r"(r3) : "r"(addr));
}
__device__ __forceinline__ uint32_t smem_u32(const void* p) {
    uint32_t a;
    asm("{ .reg .u64 t; cvta.to.shared.u64 t, %1; cvt.u32.u64 %0, t; }" : "=r"(a) : "l"(p));
    return a;
}
#define CP_ASYNC16(dst, src) \
    asm volatile("cp.async.cg.shared.global [%0], [%1], 16;" :: "r"(dst), "l"(src))
#define CP_COMMIT() asm volatile("cp.async.commit_group;" ::: "memory")
#define CP_WAIT(n)  asm volatile("cp.async.wait_group %0;" :: "n"(n) : "memory")

// =====================================================================
// fp16 mma.sync GEMM:  C = A[M,K] @ B[N,K]^T
// Block tile 128x256, BK=64, 512 threads = 16 warps (2 M x 8 N),
// warp tile 64x32. 3-stage cp.async (2-deep prefetch, 110KB in flight),
// ldmatrix.x4, rows of 72 halves (144B) -> conflict-free phases.
// MODE 0: fp32 out + bias (aux); deterministic LN partials -> g_hsum/g_hsq
// MODE 1: fp16 out = exp(alpha*acc) + deterministic row partials
// MODE 2: fp16 out = acc * rowinv[row] (aux, per batch)
// =====================================================================
#define BM 128
#define BN 256
#define BKK 64
#define LDKH 72                              // halves per SMEM row (64 + 8 pad)
#define ROWB 144                             // bytes per SMEM row
#define A_TILE_B (128 * ROWB)                // 18432 bytes
#define B_TILE_B (256 * ROWB)                // 36864 bytes
#define STAGE_B  (A_TILE_B + B_TILE_B)       // 55296 bytes
#define NSTAGE 3
#define GEMM_SMEM_BYTES (NSTAGE * STAGE_B)   // 165888
#define NTHR 512

template <int MODE>
__global__ __launch_bounds__(NTHR, 1) void gemm_kernel(
    const __half* __restrict__ Ag, const __half* __restrict__ Bg,
    const float* __restrict__ aux, void* __restrict__ Cg,
    float* __restrict__ psum, float* __restrict__ pent,
    int K, long lda, long ldb, long ldc,
    long sA, long sB, long sC, float alpha)
{
    extern __shared__ char smc[];

    const int tid = threadIdx.x;
    const int wid = tid >> 5;
    const int lid = tid & 31;
    const int wm = wid & 1;
    const int wn = wid >> 1;
    const int g = lid >> 2;
    const int t = lid & 3;

    const long bm = (long)blockIdx.x * BM;
    const long bn = (long)blockIdx.y * BN;
    const __half* A = Ag + (long)blockIdx.z * sA;
    const __half* B = Bg + (long)blockIdx.z * sB;

    const uint32_t sbase = smem_u32(smc);

    const int a_row = lid & 15;
    const int a_koff = (lid >> 4) << 3;
    const int b_row = ((lid >> 4) << 3) + (lid & 7);
    const int b_koff = lid & 8;

    float acc[4][4][4];
#pragma unroll
    for (int mt = 0; mt < 4; ++mt)
#pragma unroll
        for (int nt = 0; nt < 4; ++nt)
#pragma unroll
            for (int c = 0; c < 4; ++c) acc[mt][nt][c] = 0.0f;

    // ---- cp.async one BK=64 chunk into stage s ----
    auto copy_stage = [&](int s, long k0) {
        const uint32_t as = sbase + (uint32_t)(s * STAGE_B);
        const uint32_t bs = as + (uint32_t)A_TILE_B;
#pragma unroll
        for (int it = 0; it < 2; ++it) {
            int c = tid + it * NTHR;               // 1024 chunks: A 128 rows x 8 (8 halves)
            int m = c >> 3, k8 = (c & 7) << 3;
            CP_ASYNC16(as + (uint32_t)(m * ROWB + k8 * 2), &A[(bm + m) * lda + k0 + k8]);
        }
#pragma unroll
        for (int it = 0; it < 4; ++it) {
            int c = tid + it * NTHR;               // 2048 chunks: B 256 rows x 8
            int n = c >> 3, k8 = (c & 7) << 3;
            CP_ASYNC16(bs + (uint32_t)(n * ROWB + k8 * 2), &B[(bn + n) * ldb + k0 + k8]);
        }
    };

    // ---- compute one BK=64 chunk (4 k16 steps) from stage s ----
    auto compute = [&](int s) {
        const uint32_t as = sbase + (uint32_t)(s * STAGE_B);
        const uint32_t bs = as + (uint32_t)A_TILE_B;
#pragma unroll
        for (int ks = 0; ks < 4; ++ks) {
            const int kb = ks * 16;
            uint32_t a[4][4], b[4][2];
#pragma unroll
            for (int mt = 0; mt < 4; ++mt) {
                const int m0 = wm * 64 + mt * 16;
                ldsm_x4(a[mt][0], a[mt][1], a[mt][2], a[mt][3],
                        as + (uint32_t)((m0 + a_row) * ROWB + (kb + a_koff) * 2));
            }
#pragma unroll
            for (int np = 0; np < 2; ++np) {
                const int n0 = wn * 32 + np * 16;
                ldsm_x4(b[2 * np][0], b[2 * np][1], b[2 * np + 1][0], b[2 * np + 1][1],
                        bs + (uint32_t)((n0 + b_row) * ROWB + (kb + b_koff) * 2));
            }
#pragma unroll
            for (int mt = 0; mt < 4; ++mt)
#pragma unroll
                for (int nt = 0; nt < 4; ++nt)
                    mma_f16(acc[mt][nt], a[mt], b[nt]);
        }
    };

    const int nch = K / BKK;                    // 16 or 32
    copy_stage(0, 0); CP_COMMIT();
    copy_stage(1, BKK); CP_COMMIT();

    // steady state: wait(1) -> copy(i+2) -> compute(i)
    int s = 0, cs = 2;
    for (int i = 0; i < nch - 2; ++i) {
        CP_WAIT(1);
        __syncthreads();
        copy_stage(cs, (long)(i + 2) * BKK); CP_COMMIT();
        compute(s);
        if (++s == NSTAGE) s = 0;
        if (++cs == NSTAGE) cs = 0;
    }
    // drain: last 2 chunks
    CP_WAIT(1); __syncthreads(); compute(s); if (++s == NSTAGE) s = 0;
    CP_WAIT(0); __syncthreads(); compute(s);

    // ================= epilogues =================
    if (MODE == 1) {
        float* sp = (float*)smc;          // [128][8] sum(e)
        float* se = sp + 128 * 8;         // [128][8] sum(e*x)
        __syncthreads();
#pragma unroll
        for (int mt = 0; mt < 4; ++mt) {
            float pe0 = 0.f, pe1 = 0.f, px0 = 0.f, px1 = 0.f;
#pragma unroll
            for (int nt = 0; nt < 4; ++nt) {
                float x0 = acc[mt][nt][0] * alpha, x1 = acc[mt][nt][1] * alpha;
                float x2 = acc[mt][nt][2] * alpha, x3 = acc[mt][nt][3] * alpha;
                float e0 = __expf(x0), e1 = __expf(x1);
                float e2 = __expf(x2), e3 = __expf(x3);
                pe0 += e0 + e1;  px0 += e0 * x0 + e1 * x1;
                pe1 += e2 + e3;  px1 += e2 * x2 + e3 * x3;
                acc[mt][nt][0] = e0; acc[mt][nt][1] = e1;
                acc[mt][nt][2] = e2; acc[mt][nt][3] = e3;
            }
#pragma unroll
            for (int o = 1; o < 4; o <<= 1) {
                pe0 += __shfl_xor_sync(0xffffffffu, pe0, o);
                pe1 += __shfl_xor_sync(0xffffffffu, pe1, o);
                px0 += __shfl_xor_sync(0xffffffffu, px0, o);
                px1 += __shfl_xor_sync(0xffffffffu, px1, o);
            }
            if (t == 0) {
                int r0 = wm * 64 + mt * 16 + g;
                sp[r0 * 8 + wn] = pe0;       se[r0 * 8 + wn] = px0;
                sp[(r0 + 8) * 8 + wn] = pe1; se[(r0 + 8) * 8 + wn] = px1;
            }
        }
        __syncthreads();
        if (tid < 256) {
            int r = tid & 127, which = tid >> 7;
            const float* arr = which ? se : sp;
            float sx = 0.f;
#pragma unroll
            for (int j = 0; j < 8; ++j) sx += arr[r * 8 + j];
            long gr = (long)blockIdx.z * SEQ + bm + r;
            (which ? pent : psum)[gr * NBLK1 + blockIdx.y] = sx;
        }
        __half* Ch = (__half*)Cg + (long)blockIdx.z * sC;
#pragma unroll
        for (int mt = 0; mt < 4; ++mt) {
            const long mrow = bm + wm * 64 + mt * 16;
#pragma unroll
            for (int nt = 0; nt < 4; ++nt) {
                const long col = bn + wn * 32 + nt * 8 + 2 * t;
                *(__half2*)&Ch[(mrow + g) * ldc + col] =
                    __floats2half2_rn(acc[mt][nt][0], acc[mt][nt][1]);
                *(__half2*)&Ch[(mrow + g + 8) * ldc + col] =
                    __floats2half2_rn(acc[mt][nt][2], acc[mt][nt][3]);
            }
        }
    } else if (MODE == 2) {
        const float* rinv = aux + (long)blockIdx.z * SEQ;
        __half* Ch = (__half*)Cg + (long)blockIdx.z * sC;
#pragma unroll
        for (int mt = 0; mt < 4; ++mt) {
            const long mrow = bm + wm * 64 + mt * 16;
            const float i0 = rinv[mrow + g];
            const float i1 = rinv[mrow + g + 8];
#pragma unroll
            for (int nt = 0; nt < 4; ++nt) {
                const long col = bn + wn * 32 + nt * 8 + 2 * t;
                *(__half2*)&Ch[(mrow + g) * ldc + col] =
                    __floats2half2_rn(acc[mt][nt][0] * i0, acc[mt][nt][1] * i0);
                *(__half2*)&Ch[(mrow + g + 8) * ldc + col] =
                    __floats2half2_rn(acc[mt][nt][2] * i1, acc[mt][nt][3] * i1);
            }
        }
    } else {
        // MODE 0: write h (fp32, +bias) and deterministic LN partials
        float* hs = (float*)smc;          // [128][8] sum(h)
        float* hq = hs + 128 * 8;         // [128][8] sum(h^2)
        __syncthreads();
        float* Cf = (float*)Cg + (long)blockIdx.z * sC;
#pragma unroll
        for (int mt = 0; mt < 4; ++mt) {
            const long mrow = bm + wm * 64 + mt * 16;
            float s0 = 0.f, q0 = 0.f, s1 = 0.f, q1 = 0.f;
#pragma unroll
            for (int nt = 0; nt < 4; ++nt) {
                const long col = bn + wn * 32 + nt * 8 + 2 * t;
                float b0 = aux[col], b1 = aux[col + 1];
                float2 v0, v1;
                v0.x = acc[mt][nt][0] * alpha + b0; v0.y = acc[mt][nt][1] * alpha + b1;
                v1.x = acc[mt][nt][2] * alpha + b0; v1.y = acc[mt][nt][3] * alpha + b1;
                s0 += v0.x + v0.y;  q0 += v0.x * v0.x + v0.y * v0.y;
                s1 += v1.x + v1.y;  q1 += v1.x * v1.x + v1.y * v1.y;
                *(float2*)&Cf[(mrow + g) * ldc + col] = v0;
                *(float2*)&Cf[(mrow + g + 8) * ldc + col] = v1;
            }
#pragma unroll
            for (int o = 1; o < 4; o <<= 1) {
                s0 += __shfl_xor_sync(0xffffffffu, s0, o);
                q0 += __shfl_xor_sync(0xffffffffu, q0, o);
                s1 += __shfl_xor_sync(0xffffffffu, s1, o);
                q1 += __shfl_xor_sync(0xffffffffu, q1, o);
            }
            if (t == 0) {
                int r0 = wm * 64 + mt * 16 + g;
                hs[r0 * 8 + wn] = s0;       hq[r0 * 8 + wn] = q0;
                hs[(r0 + 8) * 8 + wn] = s1; hq[(r0 + 8) * 8 + wn] = q1;
            }
        }
        __syncthreads();
        if (tid < 256) {
            int r = tid & 127, which = tid >> 7;
            const float* arr = which ? hq : hs;
            float sx = 0.f;
#pragma unroll
            for (int j = 0; j < 8; ++j) sx += arr[r * 8 + j];
            long gr = bm + r;   // MODE 0 runs with blockIdx.z == 0, M = NROWS
            (which ? g_hsq : g_hsum)[gr * NBLK3 + blockIdx.y] = sx;
        }
    }
}

// =====================================================================
// rowstat: combine partials per row -> rowinv, rowent
// =====================================================================
__global__ __launch_bounds__(256) void rowstat_kernel() {
    int r = blockIdx.x * 256 + threadIdx.x;
    if (r < NROWS) {
        float s = 0.f, w = 0.f;
#pragma unroll
        for (int j = 0; j < NBLK1; ++j) { s += g_psum[r * NBLK1 + j]; w += g_pent[r * NBLK1 + j]; }
        g_rowinv[r] = 1.0f / s;
        g_rowent[r] = __logf(s) - w / s;
    }
}

// =====================================================================
// pre-pass: merged Q/K float -> half (grid.y selects tensor), 4x ILP
// =====================================================================
__global__ __launch_bounds__(512) void f2h2_kernel(
    const float4* __restrict__ in0, const float4* __restrict__ in1,
    __half2* __restrict__ out0, __half2* __restrict__ out1, long n4)
{
    const float4* in = blockIdx.y ? in1 : in0;
    __half2* out = blockIdx.y ? out1 : out0;
    long base = (long)blockIdx.x * 2048 + threadIdx.x;
#pragma unroll
    for (int j = 0; j < 4; ++j) {
        long i = base + j * 512;
        if (i < n4) {
            float4 v = in[i];
            out[2 * i]     = __floats2half2_rn(v.x, v.y);
            out[2 * i + 1] = __floats2half2_rn(v.z, v.w);
        }
    }
}

__global__ __launch_bounds__(256) void transpose_f2h_kernel(
    const float* __restrict__ in, __half* __restrict__ out, int R, int C, long sz)
{
    __shared__ float tbuf[32][33];
    const float* ip = in + (long)blockIdx.z * sz;
    __half* op = out + (long)blockIdx.z * sz;
    int c0 = blockIdx.x * 32, r0 = blockIdx.y * 32;
    int tx = threadIdx.x, ty = threadIdx.y; // 32 x 8
#pragma unroll
    for (int j = 0; j < 32; j += 8) tbuf[ty + j][tx] = ip[(long)(r0 + ty + j) * C + c0 + tx];
    __syncthreads();
#pragma unroll
    for (int j = 0; j < 32; j += 8)
        op[(long)(c0 + ty + j) * R + r0 + tx] = __float2half_rn(tbuf[tx][ty + j]);
}

// =====================================================================
// reductions + syntony + layernorm
// =====================================================================
__device__ __forceinline__ float warpReduceSum(float v) {
#pragma unroll
    for (int o = 16; o > 0; o >>= 1) v += __shfl_xor_sync(0xffffffffu, v, o);
    return v;
}
__device__ __forceinline__ float blockReduceSum(float v) {
    __shared__ float sh[32];
    int lane = threadIdx.x & 31, w = threadIdx.x >> 5;
    v = warpReduceSum(v);
    if (lane == 0) sh[w] = v;
    __syncthreads();
    int nw = (blockDim.x + 31) >> 5;
    float r = (threadIdx.x < nw) ? sh[threadIdx.x] : 0.0f;
    if (w == 0) r = warpReduceSum(r);
    if (threadIdx.x == 0) sh[0] = r;
    __syncthreads();
    float out = sh[0];
    __syncthreads();
    return out;
}

__global__ __launch_bounds__(512) void syntony_kernel(float* __restrict__ out, long tail_off, int tail_cnt) {
    float s = 0.0f;
    for (int i = threadIdx.x; i < NROWS; i += 512) s += g_rowent[i];
    s = blockReduceSum(s);
    if (threadIdx.x == 0) {
        float mean = s / (float)NROWS;
        float syn = 1.0f - mean / logf((float)SEQ);
        syn = fminf(fmaxf(syn, 0.0f), 1.0f);
        for (int i = 0; i < tail_cnt; ++i) out[tail_off + i] = syn;
    }
}

// layernorm using precomputed partials: pure streaming pass, no reductions
__global__ __launch_bounds__(256) void layernorm_kernel(
    float* __restrict__ H, const float* __restrict__ gamma, const float* __restrict__ beta)
{
    const long row = blockIdx.x;
    float s = 0.f, q = 0.f;
#pragma unroll
    for (int j = 0; j < NBLK3; ++j) { s += g_hsum[row * NBLK3 + j]; q += g_hsq[row * NBLK3 + j]; }
    const float mu = s * (1.0f / DMODEL);
    const float var = fmaxf(q * (1.0f / DMODEL) - mu * mu, 0.0f);
    const float inv = rsqrtf(var + EPS_LN);

    float4* h4 = (float4*)(H + row * (long)DMODEL);
    const int tid = threadIdx.x;
    float4 x = h4[tid];
    float4 gm = ((const float4*)gamma)[tid];
    float4 bt = ((const float4*)beta)[tid];
    float4 o;
    o.x = (x.x - mu) * inv * gm.x + bt.x;
    o.y = (x.y - mu) * inv * gm.y + bt.y;
    o.z = (x.z - mu) * inv * gm.z + bt.z;
    o.w = (x.w - mu) * inv * gm.w + bt.w;
    h4[tid] = o;
}

// =====================================================================
// launch
// =====================================================================
extern "C" void kernel_launch(void* const* d_in, const int* in_sizes, int n_in,
                              void* d_out, int out_size) {
    const float* q      = (const float*)d_in[0];
    const float* k      = (const float*)d_in[1];
    const float* v      = (const float*)d_in[2];
    const float* harm_w = (const float*)d_in[3];
    const float* harm_b = (const float*)d_in[4];
    const float* gamma  = (const float*)d_in[5];
    const float* beta   = (const float*)d_in[6];
    float* out = (float*)d_out;

    __half *qh, *kh, *vth, *wth, *ph, *aoh;
    float *psum, *pent, *rowinv;
    cudaGetSymbolAddress((void**)&qh, g_qh);
    cudaGetSymbolAddress((void**)&kh, g_kh);
    cudaGetSymbolAddress((void**)&vth, g_vth);
    cudaGetSymbolAddress((void**)&wth, g_wth);
    cudaGetSymbolAddress((void**)&ph, g_ph);
    cudaGetSymbolAddress((void**)&aoh, g_aoh);
    cudaGetSymbolAddress((void**)&psum, g_psum);
    cudaGetSymbolAddress((void**)&pent, g_pent);
    cudaGetSymbolAddress((void**)&rowinv, g_rowinv);

    cudaFuncSetAttribute(gemm_kernel<0>, cudaFuncAttributeMaxDynamicSharedMemorySize, GEMM_SMEM_BYTES);
    cudaFuncSetAttribute(gemm_kernel<1>, cudaFuncAttributeMaxDynamicSharedMemorySize, GEMM_SMEM_BYTES);
    cudaFuncSetAttribute(gemm_kernel<2>, cudaFuncAttributeMaxDynamicSharedMemorySize, GEMM_SMEM_BYTES);

    static cudaStream_t s1 = nullptr;
    static cudaEvent_t evFork = nullptr, evJoin = nullptr;
    if (!s1) {
        cudaStreamCreateWithFlags(&s1, cudaStreamNonBlocking);
        cudaEventCreateWithFlags(&evFork, cudaEventDisableTiming);
        cudaEventCreateWithFlags(&evJoin, cudaEventDisableTiming);
    }

    const long sQK = (long)SEQ * DMODEL;
    const long sS  = (long)SEQ * SEQ;
    const long BSD = (long)BATCH * SEQ * DMODEL;

    // ---- fork: V/W transpose+convert on side stream (overlaps GEMM1) ----
    cudaEventRecord(evFork, 0);
    cudaStreamWaitEvent(s1, evFork, 0);
    {
        dim3 blk(32, 8);
        transpose_f2h_kernel<<<dim3(DMODEL / 32, DMODEL / 32, 1), blk, 0, s1>>>(
            harm_w, wth, DMODEL, DMODEL, 0L);
        transpose_f2h_kernel<<<dim3(DMODEL / 32, SEQ / 32, BATCH), blk, 0, s1>>>(
            v, vth, SEQ, DMODEL, sQK);
    }
    cudaEventRecord(evJoin, s1);

    // ---- main stream: Q/K convert -> GEMM1 -> rowstat ----
    {
        long n4 = BSD / 4;
        dim3 g2((unsigned)((n4 + 2047) / 2048), 2);
        f2h2_kernel<<<g2, 512>>>((const float4*)q, (const float4*)k,
                                 (__half2*)qh, (__half2*)kh, n4);
    }
    // 1) expP = exp(QK^T/32) fp16 + row partial stats
    {
        dim3 grid(SEQ / BM, SEQ / BN, BATCH);
        gemm_kernel<1><<<grid, NTHR, GEMM_SMEM_BYTES>>>(
            qh, kh, nullptr, ph, psum, pent,
            DMODEL, DMODEL, DMODEL, SEQ, sQK, sQK, sS, 1.0f / 32.0f);
    }
    // 2) row stats
    rowstat_kernel<<<NROWS / 256, 256>>>();
    // 3) syntony scalar -> tail of d_out
    {
        int tail = (int)((long)out_size - BSD);
        if (tail > 0) syntony_kernel<<<1, 512>>>(out, BSD, tail);
    }
    // ---- join: V^T / W^T ready before GEMM2/GEMM3 ----
    cudaStreamWaitEvent(0, evJoin, 0);
    // 4) attout = (expP @ V) * rowinv  -> fp16
    {
        dim3 grid(SEQ / BM, DMODEL / BN, BATCH);
        gemm_kernel<2><<<grid, NTHR, GEMM_SMEM_BYTES>>>(
            ph, vth, rowinv, aoh, nullptr, nullptr,
            SEQ, SEQ, SEQ, DMODEL, sS, sQK, sQK, 1.0f);
    }
    // 5) h = attout @ W + b -> d_out fp32, + LN partial stats
    {
        dim3 grid((BATCH * SEQ) / BM, DMODEL / BN, 1);
        gemm_kernel<0><<<grid, NTHR, GEMM_SMEM_BYTES>>>(
            aoh, wth, harm_b, out, nullptr, nullptr,
            DMODEL, DMODEL, DMODEL, DMODEL, 0L, 0L, 0L, 1.0f);
    }
    // 6) layernorm in-place on d_out (streaming; stats precomputed)
    layernorm_kernel<<<BATCH * SEQ, 256>>>(out, gamma, beta);
}